// round 6
// baseline (speedup 1.0000x reference)
#include <cuda_runtime.h>
#include <cuda_fp16.h>

#define NN 100000
#define NE 1600000
#define NBLK 592                        // 148 SMs * 4 resident blocks
#define CHUNK ((NN + NBLK - 1) / NBLK)  // 169 nodes per block (<=256)
#define GTILES ((NN + 127) / 128)       // 782 gemm tiles

// ---------------- scratch (static __device__, no allocs) ----------------
struct Zeroed {
    int cnt[NN];        // hist counts
    int cur[NN];        // fill cursors
    float stats[256];   // layer1 sum/sumsq [0:128), layer2 [128:256)
    unsigned bar;       // grid barrier counter
};
__device__ Zeroed g_z;

__device__ __half g_h16[NN * 64];       // GEMM output (pre-aggregate), fp16
__device__ float  g_agg[NN * 64];       // aggregated output, fp32
__device__ int2   g_edges[NE];          // CSR payload: {src, __float_as_int(edge_norm)}
__device__ int    g_rowptr[NN + 1];
__device__ float  g_dis[NN];
__device__ float  g_selfnorm[NN];
__device__ int    g_bsum[NBLK];

// shared memory carve (dynamic): Bp 32KB | As 18KB | sAB 512B
#define SM_BP 0
#define SM_AS 32768
#define SM_SAB (32768 + 18432)
#define SMEM_TOTAL (32768 + 18432 + 512)

// ---------------- helpers ----------------
__device__ __forceinline__ unsigned f2tf32(float x) {
    unsigned r;
    asm("cvt.rna.tf32.f32 %0, %1;" : "=r"(r) : "f"(x));
    return r;
}

__device__ __forceinline__ void mma_tf32(float* d, const unsigned* a, const unsigned* b) {
    asm volatile(
        "mma.sync.aligned.m16n8k8.row.col.f32.tf32.tf32.f32 "
        "{%0,%1,%2,%3}, {%4,%5,%6,%7}, {%8,%9}, {%0,%1,%2,%3};"
        : "+f"(d[0]), "+f"(d[1]), "+f"(d[2]), "+f"(d[3])
        : "r"(a[0]), "r"(a[1]), "r"(a[2]), "r"(a[3]), "r"(b[0]), "r"(b[1]));
}

// L1-bypassing async copy (data rewritten within the launch must stay L2-coherent)
__device__ __forceinline__ void cp16cg(void* smem, const void* gmem) {
    unsigned s = (unsigned)__cvta_generic_to_shared(smem);
    asm volatile("cp.async.cg.shared.global [%0], [%1], 16;" :: "r"(s), "l"(gmem));
}

__device__ __forceinline__ __half2 ldcg_h2(const __half2* p) {
    unsigned u = __ldcg((const unsigned*)p);
    return *(__half2*)&u;
}

__device__ __forceinline__ int edge_idx(const void* ei, int i, int is64) {
    return is64 ? (int)((const long long*)ei)[i] : ((const int*)ei)[i];
}

// software grid barrier (all NBLK blocks resident)
__device__ __forceinline__ void gridbar(unsigned goal) {
    __threadfence();
    __syncthreads();
    if (threadIdx.x == 0) {
        atomicAdd(&g_z.bar, 1u);
        while (*(volatile unsigned*)&g_z.bar < goal) __nanosleep(64);
    }
    __syncthreads();
    __threadfence();
}

// ---------------- GEMM phase: out = act(A) @ W + bias, fp16 out ----------------
// grid-stride over GTILES 128-row tiles; W permuted once per block per layer.
template <int K, int NT, int BN, int STAGES>
__device__ __forceinline__ void gemm_phase(const float* __restrict__ A,
                                           const float* __restrict__ W,
                                           const float* __restrict__ bias,
                                           __half* __restrict__ out,
                                           const float* __restrict__ gamma,
                                           const float* __restrict__ beta,
                                           int soff, char* smem) {
    constexpr int N = NT * 8;
    constexpr int NK8 = K / 8;
    unsigned* Bp = (unsigned*)(smem + SM_BP);   // [kstep][ntile][lane][2]
    float* As = (float*)(smem + SM_AS);         // STAGES x 128 x 12 (stride-12 rows)
    float* sA = (float*)(smem + SM_SAB);
    float* sB = sA + 64;

    int tid = threadIdx.x;
    int lane = tid & 31;
    int warp = tid >> 5;

    // permute + convert W into exact B-fragment layout (once per layer)
    for (int i = tid; i < NK8 * NT * 32; i += 256) {
        int l = i & 31;
        int t = (i >> 5) % NT;
        int ks = i / (32 * NT);
        int kk = ks * 8 + (l & 3);
        int n = t * 8 + (l >> 2);
        Bp[i * 2 + 0] = f2tf32(W[kk * N + n]);
        Bp[i * 2 + 1] = f2tf32(W[(kk + 4) * N + n]);
    }
    if (BN) {
        if (tid < 64) {
            float mu = g_z.stats[soff + tid] * (1.0f / NN);
            float var = g_z.stats[soff + 64 + tid] * (1.0f / NN) - mu * mu;
            float a = gamma[tid] * rsqrtf(var + 1e-5f);
            sA[tid] = a;
            sB[tid] = beta[tid] - mu * a;
        }
    }
    __syncthreads();

    int srow = tid >> 1;      // 0..127
    int shalf = tid & 1;      // 16B chunk within row pair
    float* sdst = &As[srow * 12 + shalf * 4];

    for (int tile = blockIdx.x; tile < GTILES; tile += NBLK) {
        int m0 = tile * 128;
        int sm = m0 + srow;
        if (sm > NN - 1) sm = NN - 1;
        const float* sbase = A + (size_t)sm * K + shalf * 4;

        float acc[NT][4];
#pragma unroll
        for (int t = 0; t < NT; t++)
#pragma unroll
            for (int j = 0; j < 4; j++) acc[t][j] = 0.f;

#pragma unroll
        for (int s = 0; s < STAGES - 1; s++) {
            cp16cg(sdst + s * 128 * 12, sbase + s * 8);
            asm volatile("cp.async.commit_group;");
        }

        for (int ks = 0; ks < NK8; ks++) {
            asm volatile("cp.async.wait_group %0;" :: "n"(STAGES - 2));
            __syncthreads();
            int nxt = ks + STAGES - 1;
            if (nxt < NK8)
                cp16cg(sdst + (nxt % STAGES) * 128 * 12, sbase + nxt * 8);
            asm volatile("cp.async.commit_group;");

            const float* as = &As[(ks % STAGES) * 128 * 12];
            int r = warp * 16 + (lane >> 2);
            int cc = lane & 3;
            float f0 = as[r * 12 + cc];
            float f1 = as[(r + 8) * 12 + cc];
            float f2 = as[r * 12 + cc + 4];
            float f3 = as[(r + 8) * 12 + cc + 4];
            if (BN) {
                int k = ks * 8;
                float a0 = sA[k + cc], b0 = sB[k + cc];
                float a1 = sA[k + cc + 4], b1 = sB[k + cc + 4];
                f0 = fmaxf(fmaf(f0, a0, b0), 0.f);
                f1 = fmaxf(fmaf(f1, a0, b0), 0.f);
                f2 = fmaxf(fmaf(f2, a1, b1), 0.f);
                f3 = fmaxf(fmaf(f3, a1, b1), 0.f);
            }
            unsigned a[4] = { f2tf32(f0), f2tf32(f1), f2tf32(f2), f2tf32(f3) };
            const unsigned* bp = &Bp[ks * NT * 64 + lane * 2];
#pragma unroll
            for (int t = 0; t < NT; t++) {
                unsigned bb[2] = { bp[t * 64], bp[t * 64 + 1] };
                mma_tf32(acc[t], a, bb);
            }
        }

        // epilogue: pack to half2
        int r0 = m0 + warp * 16 + (lane >> 2);
        int c0 = (lane & 3) * 2;
#pragma unroll
        for (int t = 0; t < NT; t++) {
            int col = t * 8 + c0;
            float2 bv = *(const float2*)(bias + col);
            if (r0 < NN) {
                __half2 o = __floats2half2_rn(acc[t][0] + bv.x, acc[t][1] + bv.y);
                *(__half2*)(out + (size_t)r0 * N + col) = o;
            }
            if (r0 + 8 < NN) {
                __half2 o = __floats2half2_rn(acc[t][2] + bv.x, acc[t][3] + bv.y);
                *(__half2*)(out + (size_t)(r0 + 8) * N + col) = o;
            }
        }
        asm volatile("cp.async.wait_group 0;");
        __syncthreads();   // As safe for next tile
    }
}

// ---------------- aggregate phase (+ fused BN stats) ----------------
// h fp16 via __ldcg (h is rewritten each layer -> must bypass L1).
template <int C, int SOFF>
__device__ __forceinline__ void agg_phase(const __half* __restrict__ h,
                                          float* __restrict__ out, char* smem) {
    constexpr int C2 = C / 2;
    int lane = threadIdx.x & 31;
    int wid = threadIdx.x >> 5;
    int warpG = blockIdx.x * 8 + wid;
    const int nwarp = NBLK * 8;
    const __half2* h2 = (const __half2*)h;
    const bool act = (lane < C2);
    float ts0 = 0.f, ts1 = 0.f, tq0 = 0.f, tq1 = 0.f;

    for (int n = warpG; n < NN; n += nwarp) {
        int beg = g_rowptr[n];
        int end = g_rowptr[n + 1];
        float a0 = 0.f, a1 = 0.f;
        int e = beg;
        for (; e + 3 < end; e += 4) {
            int2 e0 = g_edges[e];
            int2 e1 = g_edges[e + 1];
            int2 e2 = g_edges[e + 2];
            int2 e3 = g_edges[e + 3];
            if (act) {
                float2 v0 = __half22float2(ldcg_h2(h2 + (size_t)e0.x * C2 + lane));
                float2 v1 = __half22float2(ldcg_h2(h2 + (size_t)e1.x * C2 + lane));
                float2 v2 = __half22float2(ldcg_h2(h2 + (size_t)e2.x * C2 + lane));
                float2 v3 = __half22float2(ldcg_h2(h2 + (size_t)e3.x * C2 + lane));
                float w0 = __int_as_float(e0.y), w1 = __int_as_float(e1.y);
                float w2 = __int_as_float(e2.y), w3 = __int_as_float(e3.y);
                a0 = fmaf(w0, v0.x, a0); a1 = fmaf(w0, v0.y, a1);
                a0 = fmaf(w1, v1.x, a0); a1 = fmaf(w1, v1.y, a1);
                a0 = fmaf(w2, v2.x, a0); a1 = fmaf(w2, v2.y, a1);
                a0 = fmaf(w3, v3.x, a0); a1 = fmaf(w3, v3.y, a1);
            }
        }
        for (; e < end; e++) {
            int2 ed = g_edges[e];
            if (act) {
                float w = __int_as_float(ed.y);
                float2 v = __half22float2(ldcg_h2(h2 + (size_t)ed.x * C2 + lane));
                a0 = fmaf(w, v.x, a0);
                a1 = fmaf(w, v.y, a1);
            }
        }
        if (act) {
            float sn = g_selfnorm[n];
            float2 vs = __half22float2(ldcg_h2(h2 + (size_t)n * C2 + lane));
            a0 = fmaf(sn, vs.x, a0);
            a1 = fmaf(sn, vs.y, a1);
            float2 o = { a0, a1 };
            *(float2*)(out + (size_t)n * C + 2 * lane) = o;
            if (SOFF >= 0) {
                ts0 += a0;
                ts1 += a1;
                tq0 = fmaf(a0, a0, tq0);
                tq1 = fmaf(a1, a1, tq1);
            }
        }
    }

    if (SOFF >= 0) {
        float* sm = (float*)smem;   // 4 x 256 floats
        sm[0 * 256 + threadIdx.x] = ts0;
        sm[1 * 256 + threadIdx.x] = ts1;
        sm[2 * 256 + threadIdx.x] = tq0;
        sm[3 * 256 + threadIdx.x] = tq1;
        __syncthreads();
        if (threadIdx.x < 32) {
            int l = threadIdx.x;
            float s0 = 0.f, s1 = 0.f, q0 = 0.f, q1 = 0.f;
#pragma unroll
            for (int w = 0; w < 8; w++) {
                s0 += sm[0 * 256 + w * 32 + l];
                s1 += sm[1 * 256 + w * 32 + l];
                q0 += sm[2 * 256 + w * 32 + l];
                q1 += sm[3 * 256 + w * 32 + l];
            }
            atomicAdd(&g_z.stats[SOFF + 2 * l], s0);
            atomicAdd(&g_z.stats[SOFF + 2 * l + 1], s1);
            atomicAdd(&g_z.stats[SOFF + 64 + 2 * l], q0);
            atomicAdd(&g_z.stats[SOFF + 64 + 2 * l + 1], q1);
        }
        __syncthreads();
    }
}

// ---------------- persistent mega-kernel ----------------
__global__ __launch_bounds__(256, 4) void k_mega(
    const float* __restrict__ x, const void* __restrict__ ei,
    const float* __restrict__ W1, const float* __restrict__ b1,
    const float* __restrict__ g1, const float* __restrict__ be1,
    const float* __restrict__ W2, const float* __restrict__ b2,
    const float* __restrict__ g2, const float* __restrict__ be2,
    const float* __restrict__ W3, const float* __restrict__ b3,
    float* __restrict__ out) {
    extern __shared__ __align__(16) char smem[];
    int tid = threadIdx.x;
    int b = blockIdx.x;

    // int64-layout detect (node ids < 2^31: int64 => odd words all zero)
    __shared__ int s_is64;
    __shared__ int s_off;
    if (tid < 32) {
        const int* p = (const int*)ei;
        int nz = p[2 * tid + 1] != 0;
        unsigned m = __ballot_sync(0xffffffffu, nz);
        if (tid == 0) s_is64 = (m == 0);
    }
    __syncthreads();
    int is64 = s_is64;

    // ---- P0: degree histogram ----
    for (int e = b * 256 + tid; e < NE; e += NBLK * 256)
        atomicAdd(&g_z.cnt[edge_idx(ei, NE + e, is64)], 1);
    gridbar(1 * NBLK);

    // ---- P1: scan + deg init ----
    {
        int* sh = (int*)smem;
        int base = b * CHUNK;
        int len = NN - base;
        if (len < 0) len = 0;
        if (len > CHUNK) len = CHUNK;
        int v = (tid < len) ? g_z.cnt[base + tid] : 0;
        sh[tid] = v;
        __syncthreads();
#pragma unroll
        for (int off = 128; off > 0; off >>= 1) {
            if (tid < off) sh[tid] += sh[tid + off];
            __syncthreads();
        }
        if (tid == 0) g_bsum[b] = sh[0];
        gridbar(2 * NBLK);

        int part = 0;
        for (int j = tid; j < b; j += 256) part += g_bsum[j];
        __syncthreads();
        sh[tid] = part;
        __syncthreads();
#pragma unroll
        for (int off = 128; off > 0; off >>= 1) {
            if (tid < off) sh[tid] += sh[tid + off];
            __syncthreads();
        }
        if (tid == 0) s_off = sh[0];
        __syncthreads();
        int blockoff = s_off;

        sh[tid] = v;
        __syncthreads();
#pragma unroll
        for (int off = 1; off < 256; off <<= 1) {
            int xx = (tid >= off) ? sh[tid - off] : 0;
            __syncthreads();
            sh[tid] += xx;
            __syncthreads();
        }
        if (tid < len) {
            int gid = base + tid;
            g_rowptr[gid] = blockoff + sh[tid] - v;   // exclusive
            float deg = (float)v + 1.0f;
            g_dis[gid] = rsqrtf(deg);
            g_selfnorm[gid] = 1.0f / deg;
        }
        if (b == 0 && tid == 0) g_rowptr[NN] = NE;
    }
    gridbar(3 * NBLK);

    // ---- P2: CSR fill  +  GEMM layer 1 (independent work, overlapped chip-wide) ----
    for (int e = b * 256 + tid; e < NE; e += NBLK * 256) {
        int s = edge_idx(ei, e, is64);
        int d = edge_idx(ei, NE + e, is64);
        int pos = g_rowptr[d] + atomicAdd(&g_z.cur[d], 1);
        float w = g_dis[s] * g_dis[d];
        g_edges[pos] = make_int2(s, __float_as_int(w));
    }
    __syncthreads();
    gemm_phase<128, 8, 0, 2>(x, W1, b1, g_h16, nullptr, nullptr, 0, smem);
    gridbar(4 * NBLK);

    // ---- P3: aggregate 1 (+ stats bank 0) ----
    agg_phase<64, 0>(g_h16, g_agg, smem);
    gridbar(5 * NBLK);

    // ---- P4: GEMM layer 2 (BN from bank 0) ----
    gemm_phase<64, 8, 1, 3>(g_agg, W2, b2, g_h16, g1, be1, 0, smem);
    gridbar(6 * NBLK);

    // ---- P5: aggregate 2 (+ stats bank 1) ----
    agg_phase<64, 128>(g_h16, g_agg, smem);
    gridbar(7 * NBLK);

    // ---- P6: GEMM layer 3 (BN from bank 1) ----
    gemm_phase<64, 5, 1, 3>(g_agg, W3, b3, g_h16, g2, be2, 128, smem);
    gridbar(8 * NBLK);

    // ---- P7: aggregate 3 -> output ----
    agg_phase<40, -1>(g_h16, out, smem);
}

// ---------------- launch ----------------
extern "C" void kernel_launch(void* const* d_in, const int* in_sizes, int n_in,
                              void* d_out, int out_size) {
    const float* x  = (const float*)d_in[0];
    const void*  ei = d_in[1];
    const float* W1 = (const float*)d_in[2];
    const float* b1 = (const float*)d_in[3];
    const float* g1 = (const float*)d_in[4];
    const float* be1 = (const float*)d_in[5];
    const float* W2 = (const float*)d_in[6];
    const float* b2 = (const float*)d_in[7];
    const float* g2 = (const float*)d_in[8];
    const float* be2 = (const float*)d_in[9];
    const float* W3 = (const float*)d_in[10];
    const float* b3 = (const float*)d_in[11];
    float* out = (float*)d_out;

    void* p_z = nullptr;
    cudaGetSymbolAddress(&p_z, g_z);

    static int configured = 0;
    if (!configured) {
        cudaFuncSetAttribute(k_mega, cudaFuncAttributeMaxDynamicSharedMemorySize, SMEM_TOTAL);
        configured = 1;
    }

    cudaMemsetAsync(p_z, 0, sizeof(Zeroed));  // counters + cursors + stats + barrier
    k_mega<<<NBLK, 256, SMEM_TOTAL>>>(x, ei, W1, b1, g1, be1, W2, b2, g2, be2, W3, b3, out);
}

// round 7
// speedup vs baseline: 1.2467x; 1.2467x over previous
#include <cuda_runtime.h>
#include <cuda_fp16.h>

#define NN 100000
#define NE 1600000
#define SBLK 98   // number of 1024-wide scan blocks

// ---------------- scratch (static __device__, no allocs) ----------------
struct Zeroed {
    int cnt[NN];        // hist counts
    int cur[NN];        // fill cursors
    float stats[256];   // layer1 sum/sumsq [0:128), layer2 [128:256)
};
__device__ Zeroed g_z;

__device__ __half g_h16[NN * 64];       // GEMM output (pre-aggregate), fp16
__device__ float  g_agg[NN * 64];       // aggregated output, fp32
__device__ int2   g_edges[NE];          // CSR payload: {src, __float_as_int(edge_norm)}
__device__ int    g_rowptr[NN + 1];
__device__ float  g_dis[NN];
__device__ float  g_selfnorm[NN];
__device__ int    g_bsum[128];

// ---------------- helpers ----------------
__device__ __forceinline__ unsigned f2tf32(float x) {
    unsigned r;
    asm("cvt.rna.tf32.f32 %0, %1;" : "=r"(r) : "f"(x));
    return r;
}

__device__ __forceinline__ void mma_tf32(float* d, const unsigned* a, const unsigned* b) {
    asm volatile(
        "mma.sync.aligned.m16n8k8.row.col.f32.tf32.tf32.f32 "
        "{%0,%1,%2,%3}, {%4,%5,%6,%7}, {%8,%9}, {%0,%1,%2,%3};"
        : "+f"(d[0]), "+f"(d[1]), "+f"(d[2]), "+f"(d[3])
        : "r"(a[0]), "r"(a[1]), "r"(a[2]), "r"(a[3]), "r"(b[0]), "r"(b[1]));
}

__device__ __forceinline__ void cp16(void* smem, const void* gmem) {
    unsigned s = (unsigned)__cvta_generic_to_shared(smem);
    asm volatile("cp.async.ca.shared.global [%0], [%1], 16;" :: "r"(s), "l"(gmem));
}

__device__ __forceinline__ int edge_idx(const void* ei, int i, int is64) {
    return is64 ? (int)((const long long*)ei)[i] : ((const int*)ei)[i];
}

// per-block int64-layout detect (node ids < 2^31: int64 => odd words all zero)
__device__ __forceinline__ int block_is64(const void* ei) {
    __shared__ int s_is64;
    if (threadIdx.x < 32) {
        const int* p = (const int*)ei;
        int nz = p[2 * threadIdx.x + 1] != 0;
        unsigned m = __ballot_sync(0xffffffffu, nz);
        if (threadIdx.x == 0) s_is64 = (m == 0);
    }
    __syncthreads();
    return s_is64;
}

// ---------------- CSR build (4 independent kernels; r4 structure) ----------------
__global__ void k_hist(const void* ei) {
    int is64 = block_is64(ei);
    int e = blockIdx.x * blockDim.x + threadIdx.x;
    if (e >= NE) return;
    int d = edge_idx(ei, NE + e, is64);
    atomicAdd(&g_z.cnt[d], 1);
}

__global__ void k_scanA() {
    __shared__ int s[1024];
    int t = threadIdx.x;
    int gid = blockIdx.x * 1024 + t;
    int v = (gid < NN) ? g_z.cnt[gid] : 0;
    s[t] = v;
    __syncthreads();
#pragma unroll
    for (int off = 1; off < 1024; off <<= 1) {
        int x = (t >= off) ? s[t - off] : 0;
        __syncthreads();
        s[t] += x;
        __syncthreads();
    }
    if (gid < NN) g_rowptr[gid] = s[t] - v;   // local exclusive
    if (t == 1023) g_bsum[blockIdx.x] = s[t];
}

// every block redundantly scans the 98 block sums, then finalizes its 256 nodes
__global__ void k_scanB() {
    __shared__ int s[128];
    int t = threadIdx.x;
    int v = 0;
    if (t < 128) { v = (t < SBLK) ? g_bsum[t] : 0; s[t] = v; }
    __syncthreads();
#pragma unroll
    for (int off = 1; off < 128; off <<= 1) {
        int x = (t >= off && t < 128) ? s[t - off] : 0;
        __syncthreads();
        if (t < 128) s[t] += x;
        __syncthreads();
    }
    if (t < 128) s[t] -= v;                   // exclusive
    __syncthreads();
    int gid = blockIdx.x * blockDim.x + t;
    if (gid < NN) {
        g_rowptr[gid] += s[gid >> 10];
        float deg = (float)g_z.cnt[gid] + 1.0f;
        g_dis[gid] = rsqrtf(deg);
        g_selfnorm[gid] = 1.0f / deg;
    }
    if (gid == 0) g_rowptr[NN] = NE;
}

__global__ void k_fill(const void* ei) {
    int is64 = block_is64(ei);
    int e = blockIdx.x * blockDim.x + threadIdx.x;
    if (e >= NE) return;
    int s = edge_idx(ei, e, is64);
    int d = edge_idx(ei, NE + e, is64);
    int pos = g_rowptr[d] + atomicAdd(&g_z.cur[NN + d - NN], 1);   // g_z.cur[d]
    float w = g_dis[s] * g_dis[d];
    g_edges[pos] = make_int2(s, __float_as_int(w));
}

// ---------------- tf32 MMA GEMM, 16-k staged cp.async pipeline ----------------
// out = act(A) @ W + bias, fp16 out. N = NT*8. Block: one 128-row tile, 256 threads.
// A staged in 16-k chunks, stride-20 rows (conflict-free fragment LDS).
template <int K, int NT, int BN, int STAGES>
__global__ __launch_bounds__(256) void k_gemm(const float* __restrict__ A,
                                              const float* __restrict__ W,
                                              const float* __restrict__ bias,
                                              __half* __restrict__ out,
                                              const float* __restrict__ gamma,
                                              const float* __restrict__ beta,
                                              int soff) {
    constexpr int N = NT * 8;
    constexpr int NK8 = K / 8;
    constexpr int NK16 = K / 16;
    constexpr int ASTRIDE = 20;
    constexpr int ASTAGE = 128 * ASTRIDE;      // floats per stage
    extern __shared__ __align__(16) char smem[];
    unsigned* Bp = (unsigned*)smem;                            // NK8*NT*64
    float* As = (float*)(smem + NK8 * NT * 64 * 4);            // STAGES*ASTAGE
    float* sA = As + STAGES * ASTAGE;
    float* sB = sA + 64;

    int tid = threadIdx.x;
    int lane = tid & 31;
    int warp = tid >> 5;

    // permute + convert W into exact B-fragment layout
    for (int i = tid; i < NK8 * NT * 32; i += 256) {
        int l = i & 31;
        int t = (i >> 5) % NT;
        int ks = i / (32 * NT);
        int kk = ks * 8 + (l & 3);
        int n = t * 8 + (l >> 2);
        Bp[i * 2 + 0] = f2tf32(W[kk * N + n]);
        Bp[i * 2 + 1] = f2tf32(W[(kk + 4) * N + n]);
    }
    if (BN) {
        if (tid < 64) {
            float mu = g_z.stats[soff + tid] * (1.0f / NN);
            float var = g_z.stats[soff + 64 + tid] * (1.0f / NN) - mu * mu;
            float a = gamma[tid] * rsqrtf(var + 1e-5f);
            sA[tid] = a;
            sB[tid] = beta[tid] - mu * a;
        }
    }

    float acc[NT][4];
#pragma unroll
    for (int t = 0; t < NT; t++)
#pragma unroll
        for (int j = 0; j < 4; j++) acc[t][j] = 0.f;

    int m0 = blockIdx.x * 128;
    __syncthreads();   // Bp/sA/sB ready

    // stage issue: 512 16B-chunks per stage, 2 per thread
    auto issue = [&](int st, int ks16) {
#pragma unroll
        for (int i = 0; i < 2; i++) {
            int idx = tid + i * 256;
            int row = idx >> 2, c = idx & 3;
            int m = m0 + row;
            if (m > NN - 1) m = NN - 1;
            cp16(As + st * ASTAGE + row * ASTRIDE + c * 4,
                 A + (size_t)m * K + ks16 * 16 + c * 4);
        }
        asm volatile("cp.async.commit_group;");
    };

#pragma unroll
    for (int s = 0; s < STAGES - 1 && s < NK16; s++) issue(s, s);

    for (int ks16 = 0; ks16 < NK16; ks16++) {
        asm volatile("cp.async.wait_group %0;" :: "n"(STAGES - 2));
        __syncthreads();
        int nxt = ks16 + STAGES - 1;
        if (nxt < NK16) issue(nxt % STAGES, nxt);

        const float* as = As + (ks16 % STAGES) * ASTAGE;
        int r = warp * 16 + (lane >> 2);
        int cc = lane & 3;
#pragma unroll
        for (int s = 0; s < 2; s++) {          // two k8 substeps
            int off = s * 8;
            float f0 = as[r * ASTRIDE + off + cc];
            float f1 = as[(r + 8) * ASTRIDE + off + cc];
            float f2 = as[r * ASTRIDE + off + cc + 4];
            float f3 = as[(r + 8) * ASTRIDE + off + cc + 4];
            if (BN) {
                int k = ks16 * 16 + off;
                float a0 = sA[k + cc], b0 = sB[k + cc];
                float a1 = sA[k + cc + 4], b1 = sB[k + cc + 4];
                f0 = fmaxf(fmaf(f0, a0, b0), 0.f);
                f1 = fmaxf(fmaf(f1, a0, b0), 0.f);
                f2 = fmaxf(fmaf(f2, a1, b1), 0.f);
                f3 = fmaxf(fmaf(f3, a1, b1), 0.f);
            }
            unsigned a[4] = { f2tf32(f0), f2tf32(f1), f2tf32(f2), f2tf32(f3) };
            const unsigned* bp = &Bp[(ks16 * 2 + s) * NT * 64 + lane * 2];
#pragma unroll
            for (int t = 0; t < NT; t++) {
                unsigned bb[2] = { bp[t * 64], bp[t * 64 + 1] };
                mma_tf32(acc[t], a, bb);
            }
        }
    }

    // epilogue: c0,c1 at (r, col..col+1); c2,c3 at (r+8, col..col+1); pack to half2
    int r0 = m0 + warp * 16 + (lane >> 2);
    int c0 = (lane & 3) * 2;
#pragma unroll
    for (int t = 0; t < NT; t++) {
        int col = t * 8 + c0;
        float2 bv = *(const float2*)(bias + col);
        if (r0 < NN) {
            __half2 o = __floats2half2_rn(acc[t][0] + bv.x, acc[t][1] + bv.y);
            *(__half2*)(out + (size_t)r0 * N + col) = o;
        }
        if (r0 + 8 < NN) {
            __half2 o = __floats2half2_rn(acc[t][2] + bv.x, acc[t][3] + bv.y);
            *(__half2*)(out + (size_t)(r0 + 8) * N + col) = o;
        }
    }
}

// ---------------- aggregate (+ fused BN stats): grid-stride warp-per-node ----------------
template <int C, int SOFF>
__global__ __launch_bounds__(256) void k_aggregate(const __half* __restrict__ h,
                                                   float* __restrict__ out) {
    constexpr int C2 = C / 2;
    int lane = threadIdx.x & 31;
    int wid = threadIdx.x >> 5;
    int warpG = blockIdx.x * 8 + wid;
    int nwarp = gridDim.x * 8;
    const __half2* h2 = (const __half2*)h;
    const bool act = (lane < C2);
    float ts0 = 0.f, ts1 = 0.f, tq0 = 0.f, tq1 = 0.f;

    for (int n = warpG; n < NN; n += nwarp) {
        int beg = g_rowptr[n];
        int end = g_rowptr[n + 1];
        float a0 = 0.f, a1 = 0.f;
        int e = beg;
        for (; e + 3 < end; e += 4) {       // 4-edge unroll for MLP
            int2 e0 = g_edges[e];
            int2 e1 = g_edges[e + 1];
            int2 e2 = g_edges[e + 2];
            int2 e3 = g_edges[e + 3];
            if (act) {
                float2 v0 = __half22float2(h2[(size_t)e0.x * C2 + lane]);
                float2 v1 = __half22float2(h2[(size_t)e1.x * C2 + lane]);
                float2 v2 = __half22float2(h2[(size_t)e2.x * C2 + lane]);
                float2 v3 = __half22float2(h2[(size_t)e3.x * C2 + lane]);
                float w0 = __int_as_float(e0.y), w1 = __int_as_float(e1.y);
                float w2 = __int_as_float(e2.y), w3 = __int_as_float(e3.y);
                a0 = fmaf(w0, v0.x, a0); a1 = fmaf(w0, v0.y, a1);
                a0 = fmaf(w1, v1.x, a0); a1 = fmaf(w1, v1.y, a1);
                a0 = fmaf(w2, v2.x, a0); a1 = fmaf(w2, v2.y, a1);
                a0 = fmaf(w3, v3.x, a0); a1 = fmaf(w3, v3.y, a1);
            }
        }
        for (; e < end; e++) {
            int2 ed = g_edges[e];
            if (act) {
                float w = __int_as_float(ed.y);
                float2 v = __half22float2(h2[(size_t)ed.x * C2 + lane]);
                a0 = fmaf(w, v.x, a0);
                a1 = fmaf(w, v.y, a1);
            }
        }
        if (act) {
            float sn = g_selfnorm[n];
            float2 vs = __half22float2(h2[(size_t)n * C2 + lane]);
            a0 = fmaf(sn, vs.x, a0);
            a1 = fmaf(sn, vs.y, a1);
            float2 o = { a0, a1 };
            *(float2*)(out + (size_t)n * C + 2 * lane) = o;
            if (SOFF >= 0) {
                ts0 += a0;
                ts1 += a1;
                tq0 = fmaf(a0, a0, tq0);
                tq1 = fmaf(a1, a1, tq1);
            }
        }
    }

    if (SOFF >= 0) {
        __shared__ float sm[4][256];
        sm[0][threadIdx.x] = ts0;
        sm[1][threadIdx.x] = ts1;
        sm[2][threadIdx.x] = tq0;
        sm[3][threadIdx.x] = tq1;
        __syncthreads();
        if (threadIdx.x < 32) {
            int l = threadIdx.x;
            float s0 = 0.f, s1 = 0.f, q0 = 0.f, q1 = 0.f;
#pragma unroll
            for (int w = 0; w < 8; w++) {
                s0 += sm[0][w * 32 + l];
                s1 += sm[1][w * 32 + l];
                q0 += sm[2][w * 32 + l];
                q1 += sm[3][w * 32 + l];
            }
            atomicAdd(&g_z.stats[SOFF + 2 * l], s0);
            atomicAdd(&g_z.stats[SOFF + 2 * l + 1], s1);
            atomicAdd(&g_z.stats[SOFF + 64 + 2 * l], q0);
            atomicAdd(&g_z.stats[SOFF + 64 + 2 * l + 1], q1);
        }
    }
}

// ---------------- launch ----------------
extern "C" void kernel_launch(void* const* d_in, const int* in_sizes, int n_in,
                              void* d_out, int out_size) {
    const float* x  = (const float*)d_in[0];
    const void*  ei = d_in[1];
    const float* W1 = (const float*)d_in[2];
    const float* b1 = (const float*)d_in[3];
    const float* g1 = (const float*)d_in[4];
    const float* be1 = (const float*)d_in[5];
    const float* W2 = (const float*)d_in[6];
    const float* b2 = (const float*)d_in[7];
    const float* g2 = (const float*)d_in[8];
    const float* be2 = (const float*)d_in[9];
    const float* W3 = (const float*)d_in[10];
    const float* b3 = (const float*)d_in[11];
    float* out = (float*)d_out;

    __half* h = nullptr;
    float* agg = nullptr;
    void* p_z = nullptr;
    cudaGetSymbolAddress((void**)&h, g_h16);
    cudaGetSymbolAddress((void**)&agg, g_agg);
    cudaGetSymbolAddress(&p_z, g_z);

    // dynamic smem sizes
    const int SM_G1 = 16 * 8 * 64 * 4 + 3 * 128 * 20 * 4 + 512;   // K=128,NT=8: 64000 B
    const int SM_G2 = 8 * 8 * 64 * 4 + 3 * 128 * 20 * 4 + 512;    // K=64, NT=8: 47616 B
    const int SM_G3 = 8 * 5 * 64 * 4 + 3 * 128 * 20 * 4 + 512;    // K=64, NT=5: 41472 B

    static cudaStream_t s2 = nullptr;
    static cudaEvent_t ev_fork = nullptr, ev_join = nullptr;
    if (!s2) {
        cudaStreamCreateWithFlags(&s2, cudaStreamNonBlocking);
        cudaEventCreateWithFlags(&ev_fork, cudaEventDisableTiming);
        cudaEventCreateWithFlags(&ev_join, cudaEventDisableTiming);
        cudaFuncSetAttribute(k_gemm<128, 8, 0, 3>,
                             cudaFuncAttributeMaxDynamicSharedMemorySize, SM_G1);
        cudaFuncSetAttribute(k_gemm<64, 8, 1, 3>,
                             cudaFuncAttributeMaxDynamicSharedMemorySize, SM_G2);
        cudaFuncSetAttribute(k_gemm<64, 5, 1, 3>,
                             cudaFuncAttributeMaxDynamicSharedMemorySize, SM_G3);
    }

    const int EB = (NE + 255) / 256;
    const int GB = (NN + 127) / 128;          // 782
    const int AGB = 1184;                     // grid-stride aggregate blocks

    cudaMemsetAsync(p_z, 0, sizeof(Zeroed));  // counters + cursors + stats

    // fork: GEMM1 (independent of CSR build) runs concurrently on s2
    cudaEventRecord(ev_fork, 0);
    cudaStreamWaitEvent(s2, ev_fork, 0);
    k_gemm<128, 8, 0, 3><<<GB, 256, SM_G1, s2>>>(x, W1, b1, h, nullptr, nullptr, 0);
    cudaEventRecord(ev_join, s2);

    // CSR build on main stream (overlaps with GEMM1)
    k_hist<<<EB, 256>>>(ei);
    k_scanA<<<SBLK, 1024>>>();
    k_scanB<<<(NN + 255) / 256, 256>>>();
    k_fill<<<EB, 256>>>(ei);

    // join, then the dependent chain
    cudaStreamWaitEvent(0, ev_join, 0);
    k_aggregate<64, 0><<<AGB, 256>>>(h, agg);
    k_gemm<64, 8, 1, 3><<<GB, 256, SM_G2>>>(agg, W2, b2, h, g1, be1, 0);
    k_aggregate<64, 128><<<AGB, 256>>>(h, agg);
    k_gemm<64, 5, 1, 3><<<GB, 256, SM_G3>>>(agg, W3, b3, h, g2, be2, 128);
    k_aggregate<40, -1><<<AGB, 256>>>(h, out);
}